// round 5
// baseline (speedup 1.0000x reference)
#include <cuda_runtime.h>

// Device-global scratch (no allocations). Zero-initialized at module load;
// the last block resets them so every graph replay sees clean state.
__device__ double g_acc;
__device__ unsigned int g_count;

#define NBLK 512
#define NTHR 256
#define WARPS_PER_BLK 8

// Warp-per-row streaming kernel. B=8192 rows, D=4096 fp32 (1024 float4).
// total warps = 4096 -> each warp handles 2 rows. Per lane per row:
// 32 float4 per array, unrolled x4 -> 8 LDG.128 batched in flight.
__global__ void __launch_bounds__(NTHR)
contrastive_fused_kernel(const float4* __restrict__ o1,
                         const float4* __restrict__ o2,
                         const int* __restrict__ tgt,  // int32 (jnp int64 w/o x64)
                         float* __restrict__ out,
                         int B, int d4 /* 1024 */) {
    const int lane = threadIdx.x & 31;
    const int wid  = threadIdx.x >> 5;
    const int gwarp = blockIdx.x * WARPS_PER_BLK + wid;
    const int nwarps = gridDim.x * WARPS_PER_BLK;

    double wacc = 0.0;  // per-warp (lane 0 meaningful) loss accumulator

    for (int row = gwarp; row < B; row += nwarps) {
        const size_t base = (size_t)row * (size_t)d4;
        float dot = 0.f, n1 = 0.f, n2 = 0.f;

        // 1024 float4 per row / 32 lanes = 32 per lane; unroll 4 so the
        // compiler front-batches 8 LDG.128 per iteration.
        #pragma unroll 4
        for (int i = 0; i < 32; ++i) {
            const int j = lane + (i << 5);
            const float4 a = o1[base + j];
            const float4 b = o2[base + j];
            dot = fmaf(a.x, b.x, dot); dot = fmaf(a.y, b.y, dot);
            dot = fmaf(a.z, b.z, dot); dot = fmaf(a.w, b.w, dot);
            n1  = fmaf(a.x, a.x, n1);  n1  = fmaf(a.y, a.y, n1);
            n1  = fmaf(a.z, a.z, n1);  n1  = fmaf(a.w, a.w, n1);
            n2  = fmaf(b.x, b.x, n2);  n2  = fmaf(b.y, b.y, n2);
            n2  = fmaf(b.z, b.z, n2);  n2  = fmaf(b.w, b.w, n2);
        }

        #pragma unroll
        for (int off = 16; off > 0; off >>= 1) {
            dot += __shfl_xor_sync(0xffffffffu, dot, off);
            n1  += __shfl_xor_sync(0xffffffffu, n1,  off);
            n2  += __shfl_xor_sync(0xffffffffu, n2,  off);
        }

        if (lane == 0) {
            const float cosv = dot / (sqrtf(n1) * sqrtf(n2));
            const float dist = 0.5f * (1.0f - cosv);      // 1 - 0.5*(1+cos)
            const float t    = (float)tgt[row];
            const float h    = fmaxf(0.0f, 1.0f - sqrtf(dist + 1e-9f));
            wacc += (double)(0.5f * (t * dist + (1.0f - t) * h * h));
        }
    }

    // Block-level combine: one double atomicAdd per block (512 total).
    __shared__ double s_acc[WARPS_PER_BLK];
    if (lane == 0) s_acc[wid] = wacc;
    __syncthreads();

    if (threadIdx.x == 0) {
        double bacc = 0.0;
        #pragma unroll
        for (int w = 0; w < WARPS_PER_BLK; ++w) bacc += s_acc[w];
        atomicAdd(&g_acc, bacc);

        __threadfence();
        const unsigned int done = atomicAdd(&g_count, 1u);
        if (done == gridDim.x - 1) {
            const double total = atomicAdd(&g_acc, 0.0);
            out[0] = (float)(total / (double)B);
            g_acc = 0.0;      // reset for next graph replay
            g_count = 0u;
        }
    }
}

extern "C" void kernel_launch(void* const* d_in, const int* in_sizes, int n_in,
                              void* d_out, int out_size) {
    const float4* o1 = (const float4*)d_in[0];
    const float4* o2 = (const float4*)d_in[1];
    const int* tgt = (const int*)d_in[2];
    float* out = (float*)d_out;

    const int B = in_sizes[2];           // 8192
    const int D = in_sizes[0] / B;       // 4096
    const int d4 = D / 4;                // 1024

    contrastive_fused_kernel<<<NBLK, NTHR>>>(o1, o2, tgt, out, B, d4);
}

// round 6
// speedup vs baseline: 1.1740x; 1.1740x over previous
#include <cuda_runtime.h>

#define MAX_B 8192

// Per-row losses; fully overwritten every launch (no zeroing needed).
__device__ float g_losses[MAX_B];

// One block per row (B=8192, D=4096). Pure streaming: 8 front-batched
// LDG.128 per thread, 3-way reduce, one STG per block. No atomics.
__global__ void __launch_bounds__(256)
contrastive_row_kernel(const float4* __restrict__ o1,
                       const float4* __restrict__ o2,
                       const int* __restrict__ tgt,  // int32 (jnp int64 w/o x64)
                       int d4 /* D/4 = 1024 */) {
    const int row = blockIdx.x;
    const size_t base = (size_t)row * (size_t)d4;

    // Front-batch all loads: 4 float4 per array per thread -> 8 LDG.128 in flight.
    float4 a0, a1v, a2v, a3;
    float4 b0, b1v, b2v, b3;
    {
        const int j = threadIdx.x;
        a0  = o1[base + j];
        a1v = o1[base + j + 256];
        a2v = o1[base + j + 512];
        a3  = o1[base + j + 768];
        b0  = o2[base + j];
        b1v = o2[base + j + 256];
        b2v = o2[base + j + 512];
        b3  = o2[base + j + 768];
    }

    float dot = 0.f, n1 = 0.f, n2 = 0.f;
    #define ACCUM(A, Bv)                                          \
        dot = fmaf(A.x, Bv.x, dot); dot = fmaf(A.y, Bv.y, dot);   \
        dot = fmaf(A.z, Bv.z, dot); dot = fmaf(A.w, Bv.w, dot);   \
        n1  = fmaf(A.x, A.x, n1);   n1  = fmaf(A.y, A.y, n1);     \
        n1  = fmaf(A.z, A.z, n1);   n1  = fmaf(A.w, A.w, n1);     \
        n2  = fmaf(Bv.x, Bv.x, n2); n2  = fmaf(Bv.y, Bv.y, n2);   \
        n2  = fmaf(Bv.z, Bv.z, n2); n2  = fmaf(Bv.w, Bv.w, n2);
    ACCUM(a0, b0)
    ACCUM(a1v, b1v)
    ACCUM(a2v, b2v)
    ACCUM(a3, b3)
    #undef ACCUM

    // Warp reduction (3 values).
    #pragma unroll
    for (int off = 16; off > 0; off >>= 1) {
        dot += __shfl_xor_sync(0xffffffffu, dot, off);
        n1  += __shfl_xor_sync(0xffffffffu, n1,  off);
        n2  += __shfl_xor_sync(0xffffffffu, n2,  off);
    }

    __shared__ float s_dot[8], s_n1[8], s_n2[8];
    const int wid = threadIdx.x >> 5;
    const int lid = threadIdx.x & 31;
    if (lid == 0) { s_dot[wid] = dot; s_n1[wid] = n1; s_n2[wid] = n2; }
    __syncthreads();

    if (threadIdx.x == 0) {
        float d = 0.f, q1 = 0.f, q2 = 0.f;
        #pragma unroll
        for (int w = 0; w < 8; ++w) { d += s_dot[w]; q1 += s_n1[w]; q2 += s_n2[w]; }

        const float cosv = d / (sqrtf(q1) * sqrtf(q2));
        const float dist = 0.5f * (1.0f - cosv);          // 1 - 0.5*(1+cos)
        const float t    = (float)tgt[row];
        const float h    = fmaxf(0.0f, 1.0f - sqrtf(dist + 1e-9f));
        g_losses[row] = 0.5f * (t * dist + (1.0f - t) * h * h);
    }
}

// Single-block reduction of the 8192 per-row losses (double accumulate).
__global__ void __launch_bounds__(1024)
finalize_kernel(float* __restrict__ out, int B) {
    double acc = 0.0;
    for (int i = threadIdx.x; i < B; i += 1024)
        acc += (double)g_losses[i];

    #pragma unroll
    for (int off = 16; off > 0; off >>= 1)
        acc += __shfl_xor_sync(0xffffffffu, acc, off);

    __shared__ double s[32];
    const int wid = threadIdx.x >> 5;
    const int lid = threadIdx.x & 31;
    if (lid == 0) s[wid] = acc;
    __syncthreads();

    if (threadIdx.x == 0) {
        double total = 0.0;
        #pragma unroll
        for (int w = 0; w < 32; ++w) total += s[w];
        out[0] = (float)(total / (double)B);
    }
}

extern "C" void kernel_launch(void* const* d_in, const int* in_sizes, int n_in,
                              void* d_out, int out_size) {
    const float4* o1 = (const float4*)d_in[0];
    const float4* o2 = (const float4*)d_in[1];
    const int* tgt = (const int*)d_in[2];
    float* out = (float*)d_out;

    const int B = in_sizes[2];           // 8192
    const int D = in_sizes[0] / B;       // 4096
    const int d4 = D / 4;                // 1024

    contrastive_row_kernel<<<B, 256>>>(o1, o2, tgt, d4);
    finalize_kernel<<<1, 1024>>>(out, B);
}